// round 14
// baseline (speedup 1.0000x reference)
#include <cuda_runtime.h>

// ---------------- problem constants ----------------
#define NN    1000
#define EE    8000
#define FDIM  32
#define VLEN  1680            // 60*28

// scatter grid
#define SBLK 148
#define STHR 512
#define SWARP (SBLK * STHR / 32)   // 2368 warps; ceil(9000/2368)=4 items/warp

// conv tail: block owns (conv4 row r, width half). Local widths with halo.
#define IN_ROWS 46
#define WIN 18
#define WC1 17
#define WC2 16
#define WC3 15
#define WC4 14
#define C1R 22
#define C2R 10
#define C3R 4

// ---------------- device scratch (zero-initialized at load) ----------------
__device__ float g_cnt[NN];            // INVARIANT: zero at kernel entry (re-zeroed by k_conv)
__device__ float g_hw[NN * FDIM];      // hw1 = X@W1
__device__ float g_accA[NN * FDIM];    // layer-1 aggregation
__device__ float g_accB[NN * FDIM];    // layer-2 aggregation (pre-W2)
__device__ float g_v[VLEN];
__device__ float g_fc1[1024];
__device__ float g_fc2[1024];

__device__ __forceinline__ float leaky(float v) {
    return v > 0.f ? v : 0.2f * v;
}

// ---- K1: hw1 = x(:,3:6)@W1(3:6,:) ; deg counts ; zero accA/accB ----------
__global__ void k_init(const float* __restrict__ x,
                       const float* __restrict__ W1,
                       const int* __restrict__ ei) {
    int t = blockIdx.x * blockDim.x + threadIdx.x;
    if (t < NN * FDIM) {
        int n = t >> 5, j = t & 31;
        g_hw[t] = x[n * 6 + 3] * W1[3 * 32 + j]
                + x[n * 6 + 4] * W1[4 * 32 + j]
                + x[n * 6 + 5] * W1[5 * 32 + j];
        g_accA[t] = 0.f;
        g_accB[t] = 0.f;
    }
    if (t < EE) atomicAdd(&g_cnt[ei[EE + t]], 1.0f);
}

// ---- K2: scatter layer 1: accA[c] += rsqrt((1+d_r)(1+d_c)) * hw1[r] ------
__global__ void __launch_bounds__(STHR, 1) k_scat1(const int* __restrict__ ei) {
    int t = blockIdx.x * blockDim.x + threadIdx.x;
    int warp = t >> 5, lane = t & 31;
    float vals[4]; int dsts[4];
#pragma unroll
    for (int u = 0; u < 4; u++) {
        int item = warp + u * SWARP;
        dsts[u] = -1;
        if (item < EE + NN) {
            int r, c;
            if (item < EE) { r = ei[item]; c = ei[EE + item]; }
            else           { r = item - EE; c = r; }
            float cr = g_cnt[r];
            float cc = g_cnt[c];
            float hv = g_hw[r * FDIM + lane];
            vals[u] = hv * rsqrtf((1.f + cr) * (1.f + cc));
            dsts[u] = c;
        }
    }
#pragma unroll
    for (int u = 0; u < 4; u++)
        if (dsts[u] >= 0) atomicAdd(&g_accA[dsts[u] * FDIM + lane], vals[u]);
}

// ---- K3: scatter layer 2: accB[c] += norm * leaky(accA[r] + b1) ----------
// (W2 postponed: Â·(h1@W2) == (Â·h1)@W2, applied in k_conv input stage)
__global__ void __launch_bounds__(STHR, 1) k_scat2(const int* __restrict__ ei,
                                                   const float* __restrict__ b1) {
    int t = blockIdx.x * blockDim.x + threadIdx.x;
    int warp = t >> 5, lane = t & 31;
    float bl = b1[lane];
    float vals[4]; int dsts[4];
#pragma unroll
    for (int u = 0; u < 4; u++) {
        int item = warp + u * SWARP;
        dsts[u] = -1;
        if (item < EE + NN) {
            int r, c;
            if (item < EE) { r = ei[item]; c = ei[EE + item]; }
            else           { r = item - EE; c = r; }
            float cr = g_cnt[r];
            float cc = g_cnt[c];
            float av = g_accA[r * FDIM + lane];
            vals[u] = leaky(av + bl) * rsqrtf((1.f + cr) * (1.f + cc));
            dsts[u] = c;
        }
    }
#pragma unroll
    for (int u = 0; u < 4; u++)
        if (dsts[u] >= 0) atomicAdd(&g_accB[dsts[u] * FDIM + lane], vals[u]);
}

// ---- K4: conv tail. Blocks 0..119: (row r = b>>1, width half = b&1).
//          Block 120 re-zeros g_cnt. All weights staged in smem.
__global__ void __launch_bounds__(512, 1) k_conv(
    const float* __restrict__ W2, const float* __restrict__ b2,
    const float* __restrict__ k1, const float* __restrict__ kb1,
    const float* __restrict__ k2, const float* __restrict__ kb2,
    const float* __restrict__ k3, const float* __restrict__ kb3,
    const float* __restrict__ k4, const float* __restrict__ kb4) {
    if (blockIdx.x == 120) {
        for (int i = threadIdx.x; i < NN; i += 512) g_cnt[i] = 0.f;
        return;
    }
    const int r    = blockIdx.x >> 1;
    const int B0   = (blockIdx.x & 1) * WC4;     // global col offset (0 or 14)
    const int wib  = threadIdx.x >> 5;
    const int lane = threadIdx.x & 31;

    __shared__ __align__(16) float s_w2[FDIM * FDIM];
    __shared__ float s_b2[32];
    __shared__ float s_k1[18], s_kb1[3];
    __shared__ float s_k2[108], s_kb2[6];
    __shared__ float s_k3[108], s_kb3[3];
    __shared__ float s_k4[18], s_kb4[1];
    __shared__ __align__(16) float s_in[IN_ROWS * WIN];
    __shared__ __align__(16) float s_c1[3 * C1R * WC1];
    __shared__ __align__(16) float s_c2[6 * C2R * WC2];
    __shared__ __align__(16) float s_c3[3 * C3R * WC3];

    // stage weights once
    for (int i = threadIdx.x; i < FDIM * FDIM; i += 512) s_w2[i] = W2[i];
    if (threadIdx.x < 32)  s_b2[threadIdx.x]  = b2[threadIdx.x];
    if (threadIdx.x < 18)  s_k1[threadIdx.x]  = k1[threadIdx.x];
    if (threadIdx.x < 3)   s_kb1[threadIdx.x] = kb1[threadIdx.x];
    if (threadIdx.x < 108) s_k2[threadIdx.x]  = k2[threadIdx.x];
    if (threadIdx.x < 6)   s_kb2[threadIdx.x] = kb2[threadIdx.x];
    {
        int i = threadIdx.x - 128;
        if (i >= 0 && i < 108) s_k3[i] = k3[i];
        if (i >= 108 && i < 111) s_kb3[i - 108] = kb3[i - 108];
        if (i >= 111 && i < 129) s_k4[i - 111] = k4[i - 111];
        if (i == 129) s_kb4[0] = kb4[0];
    }
    __syncthreads();

    // input slice: in[row][l] = leaky( accB[16r+row] @ W2[:,B0+l] + b2[B0+l] ),
    // lanes 0..WIN-1 active; accB row loaded into lane regs, shfl-broadcast.
    for (int row = wib; row < IN_ROWS; row += 16) {
        float a = g_accB[(16 * r + row) * FDIM + lane];
        int c = B0 + lane;                   // valid when lane < WIN (c<32)
        float s = (lane < WIN) ? s_b2[c] : 0.f;
#pragma unroll
        for (int k = 0; k < FDIM; k++) {
            float ak = __shfl_sync(0xffffffffu, a, k);
            if (lane < WIN) s += ak * s_w2[k * FDIM + c];
        }
        if (lane < WIN) s_in[row * WIN + lane] = leaky(s);
    }
    __syncthreads();

    // conv1 + relu + pool  (3 ch, 22 rows, WC1 cols)
    for (int idx = threadIdx.x; idx < 3 * C1R * WC1; idx += 512) {
        int o = idx / (C1R * WC1), rem = idx % (C1R * WC1);
        int p = rem / WC1, l = rem % WC1;
        float best = -1e30f;
#pragma unroll
        for (int rr = 0; rr < 2; rr++) {
            float s = s_kb1[o];
#pragma unroll
            for (int kh = 0; kh < 3; kh++)
#pragma unroll
                for (int kw = 0; kw < 2; kw++)
                    s += s_in[(2 * p + rr + kh) * WIN + l + kw] *
                         s_k1[(o * 3 + kh) * 2 + kw];
            best = fmaxf(best, s);
        }
        s_c1[idx] = fmaxf(best, 0.f);
    }
    __syncthreads();

    // conv2 + relu + pool  (6 ch, 10 rows, WC2 cols)
    for (int idx = threadIdx.x; idx < 6 * C2R * WC2; idx += 512) {
        int o = idx / (C2R * WC2), rem = idx % (C2R * WC2);
        int p = rem / WC2, l = rem % WC2;
        float best = -1e30f;
#pragma unroll
        for (int rr = 0; rr < 2; rr++) {
            float s = s_kb2[o];
#pragma unroll
            for (int i2 = 0; i2 < 3; i2++)
#pragma unroll
                for (int kh = 0; kh < 3; kh++)
#pragma unroll
                    for (int kw = 0; kw < 2; kw++)
                        s += s_c1[i2 * (C1R * WC1) + (2 * p + rr + kh) * WC1 + l + kw] *
                             s_k2[((o * 3 + i2) * 3 + kh) * 2 + kw];
            best = fmaxf(best, s);
        }
        s_c2[idx] = fmaxf(best, 0.f);
    }
    __syncthreads();

    // conv3 + relu + pool  (3 ch, 4 rows, WC3 cols)
    for (int idx = threadIdx.x; idx < 3 * C3R * WC3; idx += 512) {
        int o = idx / (C3R * WC3), rem = idx % (C3R * WC3);
        int p = rem / WC3, l = rem % WC3;
        float best = -1e30f;
#pragma unroll
        for (int rr = 0; rr < 2; rr++) {
            float s = s_kb3[o];
#pragma unroll
            for (int i2 = 0; i2 < 6; i2++)
#pragma unroll
                for (int kh = 0; kh < 3; kh++)
#pragma unroll
                    for (int kw = 0; kw < 2; kw++)
                        s += s_c2[i2 * (C2R * WC2) + (2 * p + rr + kh) * WC2 + l + kw] *
                             s_k3[((o * 6 + i2) * 3 + kh) * 2 + kw];
            best = fmaxf(best, s);
        }
        s_c3[idx] = fmaxf(best, 0.f);
    }
    __syncthreads();

    // conv4 + relu + pool -> g_v[r*28 + B0 + l]
    for (int l = threadIdx.x; l < WC4; l += 512) {
        float best = -1e30f;
#pragma unroll
        for (int rr = 0; rr < 2; rr++) {
            float s = s_kb4[0];
#pragma unroll
            for (int i2 = 0; i2 < 3; i2++)
#pragma unroll
                for (int kh = 0; kh < 3; kh++)
#pragma unroll
                    for (int kw = 0; kw < 2; kw++)
                        s += s_c3[i2 * (C3R * WC3) + (rr + kh) * WC3 + l + kw] *
                             s_k4[(i2 * 3 + kh) * 2 + kw];
            best = fmaxf(best, s);
        }
        g_v[r * 28 + B0 + l] = fmaxf(best, 0.f);
    }
}

// ---- FC kernels: warp per output row, input vector staged in smem --------
__global__ void __launch_bounds__(512, 1) k_fc1(const float* __restrict__ W,
                                                const float* __restrict__ b) {
    __shared__ __align__(16) float sv[VLEN];
    for (int k = threadIdx.x; k < VLEN; k += 512) sv[k] = g_v[k];
    __syncthreads();
    int warp = (blockIdx.x * 512 + threadIdx.x) >> 5;
    int lane = threadIdx.x & 31;
    const float4* wr = (const float4*)(W + (long)warp * VLEN);
    const float4* s4 = (const float4*)sv;
    float s = 0.f;
    for (int k = lane; k < VLEN / 4; k += 32) {
        float4 a = wr[k], v4 = s4[k];
        s += a.x * v4.x + a.y * v4.y + a.z * v4.z + a.w * v4.w;
    }
#pragma unroll
    for (int off = 16; off > 0; off >>= 1)
        s += __shfl_down_sync(0xffffffffu, s, off);
    if (lane == 0) g_fc1[warp] = s + b[warp];
}

__global__ void __launch_bounds__(512, 1) k_fc2(const float* __restrict__ W,
                                                const float* __restrict__ b) {
    __shared__ __align__(16) float sv[1024];
    for (int k = threadIdx.x; k < 1024; k += 512) sv[k] = g_fc1[k];
    __syncthreads();
    int warp = (blockIdx.x * 512 + threadIdx.x) >> 5;
    int lane = threadIdx.x & 31;
    const float4* wr = (const float4*)(W + (long)warp * 1024);
    const float4* s4 = (const float4*)sv;
    float s = 0.f;
    for (int k = lane; k < 256; k += 32) {
        float4 a = wr[k], v4 = s4[k];
        s += a.x * v4.x + a.y * v4.y + a.z * v4.z + a.w * v4.w;
    }
#pragma unroll
    for (int off = 16; off > 0; off >>= 1)
        s += __shfl_down_sync(0xffffffffu, s, off);
    if (lane == 0) g_fc2[warp] = s + b[warp];
}

__global__ void __launch_bounds__(1024, 1) k_fc3(const float* __restrict__ W,
                                                 const float* __restrict__ b,
                                                 float* __restrict__ out) {
    __shared__ __align__(16) float sv[1024];
    for (int k = threadIdx.x; k < 1024; k += 1024) sv[k] = g_fc2[k];
    __syncthreads();
    int warp = (blockIdx.x * 1024 + threadIdx.x) >> 5;
    int lane = threadIdx.x & 31;
    const float4* wr = (const float4*)(W + (long)warp * 1024);
    const float4* s4 = (const float4*)sv;
    float s = 0.f;
    for (int k = lane; k < 256; k += 32) {
        float4 a = wr[k], v4 = s4[k];
        s += a.x * v4.x + a.y * v4.y + a.z * v4.z + a.w * v4.w;
    }
#pragma unroll
    for (int off = 16; off > 0; off >>= 1)
        s += __shfl_down_sync(0xffffffffu, s, off);
    if (lane == 0) out[warp] = s + b[warp];
}

// ---------------- launch ----------------
extern "C" void kernel_launch(void* const* d_in, const int* in_sizes, int n_in,
                              void* d_out, int out_size) {
    const float* x   = (const float*)d_in[0];
    const int*   ei  = (const int*)d_in[1];   // int64 in reference -> int32 here
    const float* W1  = (const float*)d_in[2];
    const float* b1  = (const float*)d_in[3];
    const float* W2  = (const float*)d_in[4];
    const float* b2  = (const float*)d_in[5];
    const float* k1  = (const float*)d_in[6];
    const float* kb1 = (const float*)d_in[7];
    const float* k2  = (const float*)d_in[8];
    const float* kb2 = (const float*)d_in[9];
    const float* k3  = (const float*)d_in[10];
    const float* kb3 = (const float*)d_in[11];
    const float* k4  = (const float*)d_in[12];
    const float* kb4 = (const float*)d_in[13];
    const float* fw1 = (const float*)d_in[14];
    const float* fb1 = (const float*)d_in[15];
    const float* fw2 = (const float*)d_in[16];
    const float* fb2 = (const float*)d_in[17];
    const float* fw3 = (const float*)d_in[18];
    const float* fb3 = (const float*)d_in[19];
    float* out = (float*)d_out;

    k_init<<<64, 512>>>(x, W1, ei);
    k_scat1<<<SBLK, STHR>>>(ei);
    k_scat2<<<SBLK, STHR>>>(ei, b1);
    k_conv<<<121, 512>>>(W2, b2, k1, kb1, k2, kb2, k3, kb3, k4, kb4);
    k_fc1<<<64, 512>>>(fw1, fb1);
    k_fc2<<<64, 512>>>(fw2, fb2);
    k_fc3<<<2, 1024>>>(fw3, fb3, out);
}

// round 15
// speedup vs baseline: 1.1470x; 1.1470x over previous
#include <cuda_runtime.h>

// ---------------- problem constants ----------------
#define NN    1000
#define EE    8000
#define FDIM  32
#define VLEN  1680            // 60*28

// scatter grid
#define SBLK 148
#define STHR 512
#define SWARP (SBLK * STHR / 32)   // 2368 warps; ceil(9000/2368)=4 items/warp

// conv tail: block owns (conv4 row r, width half). Local widths with halo.
#define IN_ROWS 46
#define WIN 18
#define WC1 17
#define WC2 16
#define WC3 15
#define WC4 14
#define C1R 22
#define C2R 10
#define C3R 4

// ---------------- device scratch (zero-initialized at load) ----------------
__device__ float g_cnt[NN];            // INVARIANT: zero at kernel entry (re-zeroed by k_conv)
__device__ float g_hw[NN * FDIM];      // hw1 = X@W1
__device__ float g_accA[NN * FDIM];    // layer-1 aggregation
__device__ float g_accB[NN * FDIM];    // layer-2 aggregation (pre-W2)
__device__ float g_v[VLEN];
__device__ float g_fc1[1024];
__device__ float g_fc2[1024];

__device__ __forceinline__ float leaky(float v) {
    return v > 0.f ? v : 0.2f * v;
}

// ---- PDL primitives (sm_90+) ----
__device__ __forceinline__ void gdc_wait() {
    asm volatile("griddepcontrol.wait;" ::: "memory");
}
__device__ __forceinline__ void gdc_launch() {
    asm volatile("griddepcontrol.launch_dependents;" ::: "memory");
}

// ---- K1: hw1 = x(:,3:6)@W1(3:6,:) ; deg counts ; zero accA/accB ----------
__global__ void k_init(const float* __restrict__ x,
                       const float* __restrict__ W1,
                       const int* __restrict__ ei) {
    int t = blockIdx.x * blockDim.x + threadIdx.x;
    if (t < NN * FDIM) {
        int n = t >> 5, j = t & 31;
        g_hw[t] = x[n * 6 + 3] * W1[3 * 32 + j]
                + x[n * 6 + 4] * W1[4 * 32 + j]
                + x[n * 6 + 5] * W1[5 * 32 + j];
        g_accA[t] = 0.f;
        g_accB[t] = 0.f;
    }
    if (t < EE) atomicAdd(&g_cnt[ei[EE + t]], 1.0f);
    gdc_launch();
}

// ---- K2: scatter layer 1: accA[c] += rsqrt((1+d_r)(1+d_c)) * hw1[r] ------
__global__ void __launch_bounds__(STHR, 1) k_scat1(const int* __restrict__ ei) {
    int t = blockIdx.x * blockDim.x + threadIdx.x;
    int warp = t >> 5, lane = t & 31;
    // prologue: index loads (independent of predecessor)
    int rs[4], cs[4];
#pragma unroll
    for (int u = 0; u < 4; u++) {
        int item = warp + u * SWARP;
        rs[u] = -1;
        if (item < EE + NN) {
            if (item < EE) { rs[u] = ei[item]; cs[u] = ei[EE + item]; }
            else           { rs[u] = item - EE; cs[u] = rs[u]; }
        }
    }
    gdc_wait();   // g_cnt / g_hw ready
    float vals[4];
#pragma unroll
    for (int u = 0; u < 4; u++) {
        if (rs[u] >= 0) {
            float cr = g_cnt[rs[u]];
            float cc = g_cnt[cs[u]];
            float hv = g_hw[rs[u] * FDIM + lane];
            vals[u] = hv * rsqrtf((1.f + cr) * (1.f + cc));
        }
    }
#pragma unroll
    for (int u = 0; u < 4; u++)
        if (rs[u] >= 0) atomicAdd(&g_accA[cs[u] * FDIM + lane], vals[u]);
    gdc_launch();
}

// ---- K3: scatter layer 2: accB[c] += norm * leaky(accA[r] + b1) ----------
// (W2 postponed: Â·(h1@W2) == (Â·h1)@W2, applied in k_conv input stage)
__global__ void __launch_bounds__(STHR, 1) k_scat2(const int* __restrict__ ei,
                                                   const float* __restrict__ b1) {
    int t = blockIdx.x * blockDim.x + threadIdx.x;
    int warp = t >> 5, lane = t & 31;
    // prologue: indices + bias + degree counts (g_cnt set two kernels ago —
    // but only k_scat1 is the programmatic predecessor; g_cnt was complete
    // before k_scat1 even started, so reading it pre-wait is STILL unsafe
    // only w.r.t. k_scat1's writes. k_scat1 never writes g_cnt => safe.)
    float bl = b1[lane];
    int rs[4], cs[4];
    float nrm[4];
#pragma unroll
    for (int u = 0; u < 4; u++) {
        int item = warp + u * SWARP;
        rs[u] = -1;
        if (item < EE + NN) {
            if (item < EE) { rs[u] = ei[item]; cs[u] = ei[EE + item]; }
            else           { rs[u] = item - EE; cs[u] = rs[u]; }
            float cr = g_cnt[rs[u]];
            float cc = g_cnt[cs[u]];
            nrm[u] = rsqrtf((1.f + cr) * (1.f + cc));
        }
    }
    gdc_wait();   // g_accA ready
    float vals[4];
#pragma unroll
    for (int u = 0; u < 4; u++) {
        if (rs[u] >= 0) {
            float av = g_accA[rs[u] * FDIM + lane];
            vals[u] = leaky(av + bl) * nrm[u];
        }
    }
#pragma unroll
    for (int u = 0; u < 4; u++)
        if (rs[u] >= 0) atomicAdd(&g_accB[cs[u] * FDIM + lane], vals[u]);
    gdc_launch();
}

// ---- K4: conv tail. Blocks 0..119: (row r = b>>1, width half = b&1).
//          Block 120 re-zeros g_cnt. All weights staged in smem pre-wait.
__global__ void __launch_bounds__(512, 1) k_conv(
    const float* __restrict__ W2, const float* __restrict__ b2,
    const float* __restrict__ k1, const float* __restrict__ kb1,
    const float* __restrict__ k2, const float* __restrict__ kb2,
    const float* __restrict__ k3, const float* __restrict__ kb3,
    const float* __restrict__ k4, const float* __restrict__ kb4) {
    if (blockIdx.x == 120) {
        // must not clear g_cnt while scat kernels may read it -> after wait
        gdc_wait();
        for (int i = threadIdx.x; i < NN; i += 512) g_cnt[i] = 0.f;
        gdc_launch();
        return;
    }
    const int r    = blockIdx.x >> 1;
    const int B0   = (blockIdx.x & 1) * WC4;     // global col offset (0 or 14)
    const int wib  = threadIdx.x >> 5;
    const int lane = threadIdx.x & 31;

    __shared__ __align__(16) float s_w2[FDIM * FDIM];
    __shared__ float s_b2[32];
    __shared__ float s_k1[18], s_kb1[3];
    __shared__ float s_k2[108], s_kb2[6];
    __shared__ float s_k3[108], s_kb3[3];
    __shared__ float s_k4[18], s_kb4[1];
    __shared__ __align__(16) float s_in[IN_ROWS * WIN];
    __shared__ __align__(16) float s_c1[3 * C1R * WC1];
    __shared__ __align__(16) float s_c2[6 * C2R * WC2];
    __shared__ __align__(16) float s_c3[3 * C3R * WC3];

    // prologue: stage weights (inputs, independent of predecessor)
    for (int i = threadIdx.x; i < FDIM * FDIM; i += 512) s_w2[i] = W2[i];
    if (threadIdx.x < 32)  s_b2[threadIdx.x]  = b2[threadIdx.x];
    if (threadIdx.x < 18)  s_k1[threadIdx.x]  = k1[threadIdx.x];
    if (threadIdx.x < 3)   s_kb1[threadIdx.x] = kb1[threadIdx.x];
    if (threadIdx.x < 108) s_k2[threadIdx.x]  = k2[threadIdx.x];
    if (threadIdx.x < 6)   s_kb2[threadIdx.x] = kb2[threadIdx.x];
    {
        int i = threadIdx.x - 128;
        if (i >= 0 && i < 108) s_k3[i] = k3[i];
        if (i >= 108 && i < 111) s_kb3[i - 108] = kb3[i - 108];
        if (i >= 111 && i < 129) s_k4[i - 111] = k4[i - 111];
        if (i == 129) s_kb4[0] = kb4[0];
    }
    __syncthreads();
    gdc_wait();   // g_accB ready

    // input slice: in[row][l] = leaky( accB[16r+row] @ W2[:,B0+l] + b2[B0+l] )
    for (int row = wib; row < IN_ROWS; row += 16) {
        float a = g_accB[(16 * r + row) * FDIM + lane];
        int c = B0 + lane;                   // valid when lane < WIN (c<32)
        float s = (lane < WIN) ? s_b2[c] : 0.f;
#pragma unroll
        for (int k = 0; k < FDIM; k++) {
            float ak = __shfl_sync(0xffffffffu, a, k);
            if (lane < WIN) s += ak * s_w2[k * FDIM + c];
        }
        if (lane < WIN) s_in[row * WIN + lane] = leaky(s);
    }
    __syncthreads();

    // conv1 + relu + pool  (3 ch, 22 rows, WC1 cols)
    for (int idx = threadIdx.x; idx < 3 * C1R * WC1; idx += 512) {
        int o = idx / (C1R * WC1), rem = idx % (C1R * WC1);
        int p = rem / WC1, l = rem % WC1;
        float best = -1e30f;
#pragma unroll
        for (int rr = 0; rr < 2; rr++) {
            float s = s_kb1[o];
#pragma unroll
            for (int kh = 0; kh < 3; kh++)
#pragma unroll
                for (int kw = 0; kw < 2; kw++)
                    s += s_in[(2 * p + rr + kh) * WIN + l + kw] *
                         s_k1[(o * 3 + kh) * 2 + kw];
            best = fmaxf(best, s);
        }
        s_c1[idx] = fmaxf(best, 0.f);
    }
    __syncthreads();

    // conv2 + relu + pool  (6 ch, 10 rows, WC2 cols)
    for (int idx = threadIdx.x; idx < 6 * C2R * WC2; idx += 512) {
        int o = idx / (C2R * WC2), rem = idx % (C2R * WC2);
        int p = rem / WC2, l = rem % WC2;
        float best = -1e30f;
#pragma unroll
        for (int rr = 0; rr < 2; rr++) {
            float s = s_kb2[o];
#pragma unroll
            for (int i2 = 0; i2 < 3; i2++)
#pragma unroll
                for (int kh = 0; kh < 3; kh++)
#pragma unroll
                    for (int kw = 0; kw < 2; kw++)
                        s += s_c1[i2 * (C1R * WC1) + (2 * p + rr + kh) * WC1 + l + kw] *
                             s_k2[((o * 3 + i2) * 3 + kh) * 2 + kw];
            best = fmaxf(best, s);
        }
        s_c2[idx] = fmaxf(best, 0.f);
    }
    __syncthreads();

    // conv3 + relu + pool  (3 ch, 4 rows, WC3 cols)
    for (int idx = threadIdx.x; idx < 3 * C3R * WC3; idx += 512) {
        int o = idx / (C3R * WC3), rem = idx % (C3R * WC3);
        int p = rem / WC3, l = rem % WC3;
        float best = -1e30f;
#pragma unroll
        for (int rr = 0; rr < 2; rr++) {
            float s = s_kb3[o];
#pragma unroll
            for (int i2 = 0; i2 < 6; i2++)
#pragma unroll
                for (int kh = 0; kh < 3; kh++)
#pragma unroll
                    for (int kw = 0; kw < 2; kw++)
                        s += s_c2[i2 * (C2R * WC2) + (2 * p + rr + kh) * WC2 + l + kw] *
                             s_k3[((o * 6 + i2) * 3 + kh) * 2 + kw];
            best = fmaxf(best, s);
        }
        s_c3[idx] = fmaxf(best, 0.f);
    }
    __syncthreads();

    // conv4 + relu + pool -> g_v[r*28 + B0 + l]
    for (int l = threadIdx.x; l < WC4; l += 512) {
        float best = -1e30f;
#pragma unroll
        for (int rr = 0; rr < 2; rr++) {
            float s = s_kb4[0];
#pragma unroll
            for (int i2 = 0; i2 < 3; i2++)
#pragma unroll
                for (int kh = 0; kh < 3; kh++)
#pragma unroll
                    for (int kw = 0; kw < 2; kw++)
                        s += s_c3[i2 * (C3R * WC3) + (rr + kh) * WC3 + l + kw] *
                             s_k4[(i2 * 3 + kh) * 2 + kw];
            best = fmaxf(best, s);
        }
        g_v[r * 28 + B0 + l] = fmaxf(best, 0.f);
    }
    gdc_launch();
}

// ---- FC kernels: warp per output row, input vector staged in smem --------
__global__ void __launch_bounds__(512, 1) k_fc1(const float* __restrict__ W,
                                                const float* __restrict__ b) {
    __shared__ __align__(16) float sv[VLEN];
    gdc_wait();   // g_v ready
    for (int k = threadIdx.x; k < VLEN; k += 512) sv[k] = g_v[k];
    __syncthreads();
    int warp = (blockIdx.x * 512 + threadIdx.x) >> 5;
    int lane = threadIdx.x & 31;
    const float4* wr = (const float4*)(W + (long)warp * VLEN);
    const float4* s4 = (const float4*)sv;
    float s = 0.f;
    for (int k = lane; k < VLEN / 4; k += 32) {
        float4 a = wr[k], v4 = s4[k];
        s += a.x * v4.x + a.y * v4.y + a.z * v4.z + a.w * v4.w;
    }
#pragma unroll
    for (int off = 16; off > 0; off >>= 1)
        s += __shfl_down_sync(0xffffffffu, s, off);
    if (lane == 0) g_fc1[warp] = s + b[warp];
    gdc_launch();
}

__global__ void __launch_bounds__(512, 1) k_fc2(const float* __restrict__ W,
                                                const float* __restrict__ b) {
    __shared__ __align__(16) float sv[1024];
    gdc_wait();   // g_fc1 ready
    for (int k = threadIdx.x; k < 1024; k += 512) sv[k] = g_fc1[k];
    __syncthreads();
    int warp = (blockIdx.x * 512 + threadIdx.x) >> 5;
    int lane = threadIdx.x & 31;
    const float4* wr = (const float4*)(W + (long)warp * 1024);
    const float4* s4 = (const float4*)sv;
    float s = 0.f;
    for (int k = lane; k < 256; k += 32) {
        float4 a = wr[k], v4 = s4[k];
        s += a.x * v4.x + a.y * v4.y + a.z * v4.z + a.w * v4.w;
    }
#pragma unroll
    for (int off = 16; off > 0; off >>= 1)
        s += __shfl_down_sync(0xffffffffu, s, off);
    if (lane == 0) g_fc2[warp] = s + b[warp];
    gdc_launch();
}

__global__ void __launch_bounds__(1024, 1) k_fc3(const float* __restrict__ W,
                                                 const float* __restrict__ b,
                                                 float* __restrict__ out) {
    __shared__ __align__(16) float sv[1024];
    gdc_wait();   // g_fc2 ready
    for (int k = threadIdx.x; k < 1024; k += 1024) sv[k] = g_fc2[k];
    __syncthreads();
    int warp = (blockIdx.x * 1024 + threadIdx.x) >> 5;
    int lane = threadIdx.x & 31;
    const float4* wr = (const float4*)(W + (long)warp * 1024);
    const float4* s4 = (const float4*)sv;
    float s = 0.f;
    for (int k = lane; k < 256; k += 32) {
        float4 a = wr[k], v4 = s4[k];
        s += a.x * v4.x + a.y * v4.y + a.z * v4.z + a.w * v4.w;
    }
#pragma unroll
    for (int off = 16; off > 0; off >>= 1)
        s += __shfl_down_sync(0xffffffffu, s, off);
    if (lane == 0) out[warp] = s + b[warp];
}

// ---------------- launch (PDL on every dependent edge) ----------------
template <typename... Args>
static void launch_pdl(void (*kern)(Args...), dim3 g, dim3 b, Args... args) {
    cudaLaunchConfig_t cfg = {};
    cfg.gridDim = g;
    cfg.blockDim = b;
    cfg.dynamicSmemBytes = 0;
    cfg.stream = 0;
    cudaLaunchAttribute attr[1];
    attr[0].id = cudaLaunchAttributeProgrammaticStreamSerialization;
    attr[0].val.programmaticStreamSerializationAllowed = 1;
    cfg.attrs = attr;
    cfg.numAttrs = 1;
    cudaLaunchKernelEx(&cfg, kern, args...);
}

extern "C" void kernel_launch(void* const* d_in, const int* in_sizes, int n_in,
                              void* d_out, int out_size) {
    const float* x   = (const float*)d_in[0];
    const int*   ei  = (const int*)d_in[1];   // int64 in reference -> int32 here
    const float* W1  = (const float*)d_in[2];
    const float* b1  = (const float*)d_in[3];
    const float* W2  = (const float*)d_in[4];
    const float* b2  = (const float*)d_in[5];
    const float* k1  = (const float*)d_in[6];
    const float* kb1 = (const float*)d_in[7];
    const float* k2  = (const float*)d_in[8];
    const float* kb2 = (const float*)d_in[9];
    const float* k3  = (const float*)d_in[10];
    const float* kb3 = (const float*)d_in[11];
    const float* k4  = (const float*)d_in[12];
    const float* kb4 = (const float*)d_in[13];
    const float* fw1 = (const float*)d_in[14];
    const float* fb1 = (const float*)d_in[15];
    const float* fw2 = (const float*)d_in[16];
    const float* fb2 = (const float*)d_in[17];
    const float* fw3 = (const float*)d_in[18];
    const float* fb3 = (const float*)d_in[19];
    float* out = (float*)d_out;

    k_init<<<64, 512>>>(x, W1, ei);
    launch_pdl(k_scat1, dim3(SBLK), dim3(STHR), ei);
    launch_pdl(k_scat2, dim3(SBLK), dim3(STHR), ei, b1);
    launch_pdl(k_conv, dim3(121), dim3(512),
               W2, b2, k1, kb1, k2, kb2, k3, kb3, k4, kb4);
    launch_pdl(k_fc1, dim3(64), dim3(512), fw1, fb1);
    launch_pdl(k_fc2, dim3(64), dim3(512), fw2, fb2);
    launch_pdl(k_fc3, dim3(2), dim3(1024), fw3, fb3, out);
}

// round 16
// speedup vs baseline: 1.1592x; 1.0106x over previous
#include <cuda_runtime.h>

// ---------------- problem constants ----------------
#define NN    1000
#define EE    8000
#define FDIM  32
#define VLEN  1680            // 60*28

// scatter grid
#define SBLK 148
#define STHR 512
#define SWARP (SBLK * STHR / 32)   // 2368 warps; ceil(9000/2368)=4 items/warp

// conv tail: block owns (conv4 row r, width half). Local widths with halo.
#define IN_ROWS 46
#define WIN 18
#define WC1 17
#define WC2 16
#define WC3 15
#define WC4 14
#define C1R 22
#define C2R 10
#define C3R 4

// ---------------- device scratch (zero-initialized at load) ----------------
__device__ float g_cnt[NN];            // INVARIANT: zero at kernel entry (re-zeroed by k_conv)
__device__ float g_hw[NN * FDIM];      // hw1 = X@W1
__device__ float g_accA[NN * FDIM];    // layer-1 aggregation
__device__ float g_accB[NN * FDIM];    // layer-2 aggregation (pre-W2)
__device__ float g_v[VLEN];
__device__ float g_fc1[1024];
__device__ float g_fc2[1024];

__device__ __forceinline__ float leaky(float v) {
    return v > 0.f ? v : 0.2f * v;
}

// ---- PDL primitives (sm_90+) ----
__device__ __forceinline__ void gdc_wait() {
    asm volatile("griddepcontrol.wait;" ::: "memory");
}
__device__ __forceinline__ void gdc_launch() {
    asm volatile("griddepcontrol.launch_dependents;" ::: "memory");
}

// ---- K1: hw1 = x(:,3:6)@W1(3:6,:) ; deg counts ; zero accA/accB ----------
__global__ void k_init(const float* __restrict__ x,
                       const float* __restrict__ W1,
                       const int* __restrict__ ei) {
    int t = blockIdx.x * blockDim.x + threadIdx.x;
    if (t < NN * FDIM) {
        int n = t >> 5, j = t & 31;
        g_hw[t] = x[n * 6 + 3] * W1[3 * 32 + j]
                + x[n * 6 + 4] * W1[4 * 32 + j]
                + x[n * 6 + 5] * W1[5 * 32 + j];
        g_accA[t] = 0.f;
        g_accB[t] = 0.f;
    }
    if (t < EE) atomicAdd(&g_cnt[ei[EE + t]], 1.0f);
    gdc_launch();
}

// ---- K2: scatter layer 1: accA[c] += rsqrt((1+d_r)(1+d_c)) * hw1[r] ------
__global__ void __launch_bounds__(STHR, 1) k_scat1(const int* __restrict__ ei) {
    int t = blockIdx.x * blockDim.x + threadIdx.x;
    int warp = t >> 5, lane = t & 31;
    // prologue: index loads (independent of predecessor)
    int rs[4], cs[4];
#pragma unroll
    for (int u = 0; u < 4; u++) {
        int item = warp + u * SWARP;
        rs[u] = -1;
        if (item < EE + NN) {
            if (item < EE) { rs[u] = ei[item]; cs[u] = ei[EE + item]; }
            else           { rs[u] = item - EE; cs[u] = rs[u]; }
        }
    }
    gdc_wait();   // g_cnt / g_hw ready
    float vals[4];
#pragma unroll
    for (int u = 0; u < 4; u++) {
        if (rs[u] >= 0) {
            float cr = g_cnt[rs[u]];
            float cc = g_cnt[cs[u]];
            float hv = g_hw[rs[u] * FDIM + lane];
            vals[u] = hv * rsqrtf((1.f + cr) * (1.f + cc));
        }
    }
#pragma unroll
    for (int u = 0; u < 4; u++)
        if (rs[u] >= 0) atomicAdd(&g_accA[cs[u] * FDIM + lane], vals[u]);
    gdc_launch();
}

// ---- K3: scatter layer 2: accB[c] += norm * leaky(accA[r] + b1) ----------
// (W2 postponed: Â·(h1@W2) == (Â·h1)@W2, applied in k_conv input stage)
__global__ void __launch_bounds__(STHR, 1) k_scat2(const int* __restrict__ ei,
                                                   const float* __restrict__ b1) {
    int t = blockIdx.x * blockDim.x + threadIdx.x;
    int warp = t >> 5, lane = t & 31;
    // prologue: indices + bias + degree counts (g_cnt set two kernels ago —
    // but only k_scat1 is the programmatic predecessor; g_cnt was complete
    // before k_scat1 even started, so reading it pre-wait is STILL unsafe
    // only w.r.t. k_scat1's writes. k_scat1 never writes g_cnt => safe.)
    float bl = b1[lane];
    int rs[4], cs[4];
    float nrm[4];
#pragma unroll
    for (int u = 0; u < 4; u++) {
        int item = warp + u * SWARP;
        rs[u] = -1;
        if (item < EE + NN) {
            if (item < EE) { rs[u] = ei[item]; cs[u] = ei[EE + item]; }
            else           { rs[u] = item - EE; cs[u] = rs[u]; }
            float cr = g_cnt[rs[u]];
            float cc = g_cnt[cs[u]];
            nrm[u] = rsqrtf((1.f + cr) * (1.f + cc));
        }
    }
    gdc_wait();   // g_accA ready
    float vals[4];
#pragma unroll
    for (int u = 0; u < 4; u++) {
        if (rs[u] >= 0) {
            float av = g_accA[rs[u] * FDIM + lane];
            vals[u] = leaky(av + bl) * nrm[u];
        }
    }
#pragma unroll
    for (int u = 0; u < 4; u++)
        if (rs[u] >= 0) atomicAdd(&g_accB[cs[u] * FDIM + lane], vals[u]);
    gdc_launch();
}

// ---- K4: conv tail. Blocks 0..119: (row r = b>>1, width half = b&1).
//          Block 120 re-zeros g_cnt. All weights staged in smem pre-wait.
__global__ void __launch_bounds__(512, 1) k_conv(
    const float* __restrict__ W2, const float* __restrict__ b2,
    const float* __restrict__ k1, const float* __restrict__ kb1,
    const float* __restrict__ k2, const float* __restrict__ kb2,
    const float* __restrict__ k3, const float* __restrict__ kb3,
    const float* __restrict__ k4, const float* __restrict__ kb4) {
    if (blockIdx.x == 120) {
        // must not clear g_cnt while scat kernels may read it -> after wait
        gdc_wait();
        for (int i = threadIdx.x; i < NN; i += 512) g_cnt[i] = 0.f;
        gdc_launch();
        return;
    }
    const int r    = blockIdx.x >> 1;
    const int B0   = (blockIdx.x & 1) * WC4;     // global col offset (0 or 14)
    const int wib  = threadIdx.x >> 5;
    const int lane = threadIdx.x & 31;

    __shared__ __align__(16) float s_w2[FDIM * FDIM];
    __shared__ float s_b2[32];
    __shared__ float s_k1[18], s_kb1[3];
    __shared__ float s_k2[108], s_kb2[6];
    __shared__ float s_k3[108], s_kb3[3];
    __shared__ float s_k4[18], s_kb4[1];
    __shared__ __align__(16) float s_in[IN_ROWS * WIN];
    __shared__ __align__(16) float s_c1[3 * C1R * WC1];
    __shared__ __align__(16) float s_c2[6 * C2R * WC2];
    __shared__ __align__(16) float s_c3[3 * C3R * WC3];

    // prologue: stage weights (inputs, independent of predecessor)
    for (int i = threadIdx.x; i < FDIM * FDIM; i += 512) s_w2[i] = W2[i];
    if (threadIdx.x < 32)  s_b2[threadIdx.x]  = b2[threadIdx.x];
    if (threadIdx.x < 18)  s_k1[threadIdx.x]  = k1[threadIdx.x];
    if (threadIdx.x < 3)   s_kb1[threadIdx.x] = kb1[threadIdx.x];
    if (threadIdx.x < 108) s_k2[threadIdx.x]  = k2[threadIdx.x];
    if (threadIdx.x < 6)   s_kb2[threadIdx.x] = kb2[threadIdx.x];
    {
        int i = threadIdx.x - 128;
        if (i >= 0 && i < 108) s_k3[i] = k3[i];
        if (i >= 108 && i < 111) s_kb3[i - 108] = kb3[i - 108];
        if (i >= 111 && i < 129) s_k4[i - 111] = k4[i - 111];
        if (i == 129) s_kb4[0] = kb4[0];
    }
    __syncthreads();
    gdc_wait();   // g_accB ready

    // input slice: in[row][l] = leaky( accB[16r+row] @ W2[:,B0+l] + b2[B0+l] )
    for (int row = wib; row < IN_ROWS; row += 16) {
        float a = g_accB[(16 * r + row) * FDIM + lane];
        int c = B0 + lane;                   // valid when lane < WIN (c<32)
        float s = (lane < WIN) ? s_b2[c] : 0.f;
#pragma unroll
        for (int k = 0; k < FDIM; k++) {
            float ak = __shfl_sync(0xffffffffu, a, k);
            if (lane < WIN) s += ak * s_w2[k * FDIM + c];
        }
        if (lane < WIN) s_in[row * WIN + lane] = leaky(s);
    }
    __syncthreads();

    // conv1 + relu + pool  (3 ch, 22 rows, WC1 cols)
    for (int idx = threadIdx.x; idx < 3 * C1R * WC1; idx += 512) {
        int o = idx / (C1R * WC1), rem = idx % (C1R * WC1);
        int p = rem / WC1, l = rem % WC1;
        float best = -1e30f;
#pragma unroll
        for (int rr = 0; rr < 2; rr++) {
            float s = s_kb1[o];
#pragma unroll
            for (int kh = 0; kh < 3; kh++)
#pragma unroll
                for (int kw = 0; kw < 2; kw++)
                    s += s_in[(2 * p + rr + kh) * WIN + l + kw] *
                         s_k1[(o * 3 + kh) * 2 + kw];
            best = fmaxf(best, s);
        }
        s_c1[idx] = fmaxf(best, 0.f);
    }
    __syncthreads();

    // conv2 + relu + pool  (6 ch, 10 rows, WC2 cols)
    for (int idx = threadIdx.x; idx < 6 * C2R * WC2; idx += 512) {
        int o = idx / (C2R * WC2), rem = idx % (C2R * WC2);
        int p = rem / WC2, l = rem % WC2;
        float best = -1e30f;
#pragma unroll
        for (int rr = 0; rr < 2; rr++) {
            float s = s_kb2[o];
#pragma unroll
            for (int i2 = 0; i2 < 3; i2++)
#pragma unroll
                for (int kh = 0; kh < 3; kh++)
#pragma unroll
                    for (int kw = 0; kw < 2; kw++)
                        s += s_c1[i2 * (C1R * WC1) + (2 * p + rr + kh) * WC1 + l + kw] *
                             s_k2[((o * 3 + i2) * 3 + kh) * 2 + kw];
            best = fmaxf(best, s);
        }
        s_c2[idx] = fmaxf(best, 0.f);
    }
    __syncthreads();

    // conv3 + relu + pool  (3 ch, 4 rows, WC3 cols)
    for (int idx = threadIdx.x; idx < 3 * C3R * WC3; idx += 512) {
        int o = idx / (C3R * WC3), rem = idx % (C3R * WC3);
        int p = rem / WC3, l = rem % WC3;
        float best = -1e30f;
#pragma unroll
        for (int rr = 0; rr < 2; rr++) {
            float s = s_kb3[o];
#pragma unroll
            for (int i2 = 0; i2 < 6; i2++)
#pragma unroll
                for (int kh = 0; kh < 3; kh++)
#pragma unroll
                    for (int kw = 0; kw < 2; kw++)
                        s += s_c2[i2 * (C2R * WC2) + (2 * p + rr + kh) * WC2 + l + kw] *
                             s_k3[((o * 6 + i2) * 3 + kh) * 2 + kw];
            best = fmaxf(best, s);
        }
        s_c3[idx] = fmaxf(best, 0.f);
    }
    __syncthreads();

    // conv4 + relu + pool -> g_v[r*28 + B0 + l]
    for (int l = threadIdx.x; l < WC4; l += 512) {
        float best = -1e30f;
#pragma unroll
        for (int rr = 0; rr < 2; rr++) {
            float s = s_kb4[0];
#pragma unroll
            for (int i2 = 0; i2 < 3; i2++)
#pragma unroll
                for (int kh = 0; kh < 3; kh++)
#pragma unroll
                    for (int kw = 0; kw < 2; kw++)
                        s += s_c3[i2 * (C3R * WC3) + (rr + kh) * WC3 + l + kw] *
                             s_k4[(i2 * 3 + kh) * 2 + kw];
            best = fmaxf(best, s);
        }
        g_v[r * 28 + B0 + l] = fmaxf(best, 0.f);
    }
    gdc_launch();
}

// ---- FC kernels: warp per output row, input vector staged in smem --------
__global__ void __launch_bounds__(512, 1) k_fc1(const float* __restrict__ W,
                                                const float* __restrict__ b) {
    __shared__ __align__(16) float sv[VLEN];
    gdc_wait();   // g_v ready
    for (int k = threadIdx.x; k < VLEN; k += 512) sv[k] = g_v[k];
    __syncthreads();
    int warp = (blockIdx.x * 512 + threadIdx.x) >> 5;
    int lane = threadIdx.x & 31;
    const float4* wr = (const float4*)(W + (long)warp * VLEN);
    const float4* s4 = (const float4*)sv;
    float s = 0.f;
    for (int k = lane; k < VLEN / 4; k += 32) {
        float4 a = wr[k], v4 = s4[k];
        s += a.x * v4.x + a.y * v4.y + a.z * v4.z + a.w * v4.w;
    }
#pragma unroll
    for (int off = 16; off > 0; off >>= 1)
        s += __shfl_down_sync(0xffffffffu, s, off);
    if (lane == 0) g_fc1[warp] = s + b[warp];
    gdc_launch();
}

__global__ void __launch_bounds__(512, 1) k_fc2(const float* __restrict__ W,
                                                const float* __restrict__ b) {
    __shared__ __align__(16) float sv[1024];
    gdc_wait();   // g_fc1 ready
    for (int k = threadIdx.x; k < 1024; k += 512) sv[k] = g_fc1[k];
    __syncthreads();
    int warp = (blockIdx.x * 512 + threadIdx.x) >> 5;
    int lane = threadIdx.x & 31;
    const float4* wr = (const float4*)(W + (long)warp * 1024);
    const float4* s4 = (const float4*)sv;
    float s = 0.f;
    for (int k = lane; k < 256; k += 32) {
        float4 a = wr[k], v4 = s4[k];
        s += a.x * v4.x + a.y * v4.y + a.z * v4.z + a.w * v4.w;
    }
#pragma unroll
    for (int off = 16; off > 0; off >>= 1)
        s += __shfl_down_sync(0xffffffffu, s, off);
    if (lane == 0) g_fc2[warp] = s + b[warp];
    gdc_launch();
}

__global__ void __launch_bounds__(1024, 1) k_fc3(const float* __restrict__ W,
                                                 const float* __restrict__ b,
                                                 float* __restrict__ out) {
    __shared__ __align__(16) float sv[1024];
    gdc_wait();   // g_fc2 ready
    for (int k = threadIdx.x; k < 1024; k += 1024) sv[k] = g_fc2[k];
    __syncthreads();
    int warp = (blockIdx.x * 1024 + threadIdx.x) >> 5;
    int lane = threadIdx.x & 31;
    const float4* wr = (const float4*)(W + (long)warp * 1024);
    const float4* s4 = (const float4*)sv;
    float s = 0.f;
    for (int k = lane; k < 256; k += 32) {
        float4 a = wr[k], v4 = s4[k];
        s += a.x * v4.x + a.y * v4.y + a.z * v4.z + a.w * v4.w;
    }
#pragma unroll
    for (int off = 16; off > 0; off >>= 1)
        s += __shfl_down_sync(0xffffffffu, s, off);
    if (lane == 0) out[warp] = s + b[warp];
}

// ---------------- launch (PDL on every dependent edge) ----------------
template <typename... Args>
static void launch_pdl(void (*kern)(Args...), dim3 g, dim3 b, Args... args) {
    cudaLaunchConfig_t cfg = {};
    cfg.gridDim = g;
    cfg.blockDim = b;
    cfg.dynamicSmemBytes = 0;
    cfg.stream = 0;
    cudaLaunchAttribute attr[1];
    attr[0].id = cudaLaunchAttributeProgrammaticStreamSerialization;
    attr[0].val.programmaticStreamSerializationAllowed = 1;
    cfg.attrs = attr;
    cfg.numAttrs = 1;
    cudaLaunchKernelEx(&cfg, kern, args...);
}

extern "C" void kernel_launch(void* const* d_in, const int* in_sizes, int n_in,
                              void* d_out, int out_size) {
    const float* x   = (const float*)d_in[0];
    const int*   ei  = (const int*)d_in[1];   // int64 in reference -> int32 here
    const float* W1  = (const float*)d_in[2];
    const float* b1  = (const float*)d_in[3];
    const float* W2  = (const float*)d_in[4];
    const float* b2  = (const float*)d_in[5];
    const float* k1  = (const float*)d_in[6];
    const float* kb1 = (const float*)d_in[7];
    const float* k2  = (const float*)d_in[8];
    const float* kb2 = (const float*)d_in[9];
    const float* k3  = (const float*)d_in[10];
    const float* kb3 = (const float*)d_in[11];
    const float* k4  = (const float*)d_in[12];
    const float* kb4 = (const float*)d_in[13];
    const float* fw1 = (const float*)d_in[14];
    const float* fb1 = (const float*)d_in[15];
    const float* fw2 = (const float*)d_in[16];
    const float* fb2 = (const float*)d_in[17];
    const float* fw3 = (const float*)d_in[18];
    const float* fb3 = (const float*)d_in[19];
    float* out = (float*)d_out;

    k_init<<<64, 512>>>(x, W1, ei);
    launch_pdl(k_scat1, dim3(SBLK), dim3(STHR), ei);
    launch_pdl(k_scat2, dim3(SBLK), dim3(STHR), ei, b1);
    launch_pdl(k_conv, dim3(121), dim3(512),
               W2, b2, k1, kb1, k2, kb2, k3, kb3, k4, kb4);
    launch_pdl(k_fc1, dim3(64), dim3(512), fw1, fb1);
    launch_pdl(k_fc2, dim3(64), dim3(512), fw2, fb2);
    launch_pdl(k_fc3, dim3(2), dim3(1024), fw3, fb3, out);
}